// round 1
// baseline (speedup 1.0000x reference)
#include <cuda_runtime.h>
#include <math.h>

// ----------------------------------------------------------------------------
// Radial NUFFT pipeline (exact NDFT), N=192 image, M=36864 samples.
//   A[m,x] = exp(-2*pi*i * kx[m] * p[x]),  B[m,y] = exp(-2*pi*i * ky[m] * p[y])
//   op(img)[m]   = sum_x A[m,x] * sum_y B[m,y] img[x,y]
//   adj(d)[x,y]  = sum_m conj(A[m,x]) d[m] conj(B[m,y])
//   pipe: w=1; 3x { q = op(adj(w)); w /= max(|q|,1e-20) }
//   out = adj(w * op(img)),  output (2,N,N) = (re,im)
// ----------------------------------------------------------------------------

#define NPIX   192
#define MPTS   (NPIX * NPIX)        // 36864
#define NN     (NPIX * NPIX)
#define NCHUNK 64                    // split-K chunks for adjoint
#define KCHUNK (MPTS / NCHUNK)       // 576
#define TWO_PI_F 6.28318530717958647693f

// -------------------- scratch (device globals; no allocations) --------------
static __device__ float g_Ar[MPTS * NPIX];
static __device__ float g_Ai[MPTS * NPIX];
static __device__ float g_Br[MPTS * NPIX];
static __device__ float g_Bi[MPTS * NPIX];

static __device__ float g_imgT_re[NN],  g_imgT_im[NN];    // input image, [y][x]
static __device__ float g_imgwT_re[NN], g_imgwT_im[NN];   // pipe image,  [y][x]

static __device__ float g_w[MPTS];                 // density weights (real)
static __device__ float g_dre[MPTS], g_dim[MPTS];  // adjoint input samples
static __device__ float g_sre[MPTS], g_sim[MPTS];  // op output (q / kspace)

static __device__ float g_part[NCHUNK * 2 * NN];   // adjoint split-K partials

// -------------------- build A, B ---------------------------------------------
__global__ void k_build(const float* __restrict__ traj) {
    int idx = blockIdx.x * blockDim.x + threadIdx.x;
    if (idx >= MPTS * NPIX) return;
    int m = idx / NPIX;
    int x = idx - m * NPIX;
    float p  = (float)x - 96.0f;
    float kx = traj[2 * m];
    float ky = traj[2 * m + 1];

    // exp(-2*pi*i * k * p): range-reduce phase mod 1 exactly, then fast sincos.
    float s, c, ph, r;
    ph = kx * p; r = ph - rintf(ph);
    __sincosf(TWO_PI_F * r, &s, &c);
    g_Ar[idx] = c;  g_Ai[idx] = -s;

    ph = ky * p; r = ph - rintf(ph);
    __sincosf(TWO_PI_F * r, &s, &c);
    g_Br[idx] = c;  g_Bi[idx] = -s;
}

// -------------------- image transpose (input (2,N,N) -> [y][x] planes) -------
__global__ void k_transpose_in(const float* __restrict__ xin) {
    int idx = blockIdx.x * blockDim.x + threadIdx.x;
    if (idx >= NN) return;
    int x = idx / NPIX, y = idx - x * NPIX;
    g_imgT_re[y * NPIX + x] = xin[idx];
    g_imgT_im[y * NPIX + x] = xin[NN + idx];
}

// -------------------- tiny per-sample kernels --------------------------------
__global__ void k_winit() {
    int i = blockIdx.x * blockDim.x + threadIdx.x;
    if (i < MPTS) g_w[i] = 1.0f;
}
__global__ void k_dfromw() {
    int i = blockIdx.x * blockDim.x + threadIdx.x;
    if (i < MPTS) { g_dre[i] = g_w[i]; g_dim[i] = 0.0f; }
}
__global__ void k_wupdate() {
    int i = blockIdx.x * blockDim.x + threadIdx.x;
    if (i < MPTS) {
        float qr = g_sre[i], qi = g_sim[i];
        float mag = sqrtf(qr * qr + qi * qi);
        g_w[i] = g_w[i] / fmaxf(mag, 1e-20f);
    }
}
__global__ void k_dscale() {
    int i = blockIdx.x * blockDim.x + threadIdx.x;
    if (i < MPTS) {
        float w = g_w[i];
        g_dre[i] = w * g_sre[i];
        g_dim[i] = w * g_sim[i];
    }
}

// -------------------- forward op: s[m] = sum_x A[m,x] (sum_y B[m,y] img[x,y]) -
// One block per 16 sample rows. Full x=192 kept in registers so the A-dot
// epilogue fuses in (no t materialization). src: 0 = g_imgT, 1 = g_imgwT.
__global__ void __launch_bounds__(256) k_op(int src) {
    __shared__ float sIr[16][192];
    __shared__ float sIi[16][192];
    __shared__ float sBr[16][16];
    __shared__ float sBi[16][16];

    const float* __restrict__ gTr = src ? g_imgwT_re : g_imgT_re;
    const float* __restrict__ gTi = src ? g_imgwT_im : g_imgT_im;

    int m0   = blockIdx.x * 16;
    int t    = threadIdx.x;
    int lane = t & 31;
    int wrp  = t >> 5;           // 8 warps; warp handles m_local = 2*wrp, 2*wrp+1

    float accr[2][6], acci[2][6];
#pragma unroll
    for (int a = 0; a < 2; ++a)
#pragma unroll
        for (int j = 0; j < 6; ++j) { accr[a][j] = 0.0f; acci[a][j] = 0.0f; }

    for (int y0 = 0; y0 < NPIX; y0 += 16) {
        // stage img tile [16 y][192 x] (coalesced: imgT is [y][x])
        for (int i = t; i < 16 * 192; i += 256) {
            int yl = i / 192, x = i - yl * 192;
            sIr[yl][x] = gTr[(y0 + yl) * NPIX + x];
            sIi[yl][x] = gTi[(y0 + yl) * NPIX + x];
        }
        // stage B tile [16 m][16 y]
        {
            int ml = t >> 4, yl = t & 15;
            sBr[ml][yl] = g_Br[(m0 + ml) * NPIX + y0 + yl];
            sBi[ml][yl] = g_Bi[(m0 + ml) * NPIX + y0 + yl];
        }
        __syncthreads();

#pragma unroll
        for (int k = 0; k < 16; ++k) {
            float b0r = sBr[2 * wrp][k],     b0i = sBi[2 * wrp][k];
            float b1r = sBr[2 * wrp + 1][k], b1i = sBi[2 * wrp + 1][k];
#pragma unroll
            for (int j = 0; j < 6; ++j) {
                float gr = sIr[k][lane + 32 * j];
                float gi = sIi[k][lane + 32 * j];
                accr[0][j] = fmaf(b0r, gr, accr[0][j]);
                accr[0][j] = fmaf(-b0i, gi, accr[0][j]);
                acci[0][j] = fmaf(b0r, gi, acci[0][j]);
                acci[0][j] = fmaf(b0i, gr, acci[0][j]);
                accr[1][j] = fmaf(b1r, gr, accr[1][j]);
                accr[1][j] = fmaf(-b1i, gi, accr[1][j]);
                acci[1][j] = fmaf(b1r, gi, acci[1][j]);
                acci[1][j] = fmaf(b1i, gr, acci[1][j]);
            }
        }
        __syncthreads();
    }

    // epilogue: k[m] = sum_x A[m,x] * t[m,x]  (t lives in this warp's registers)
#pragma unroll
    for (int mi = 0; mi < 2; ++mi) {
        int m = m0 + 2 * wrp + mi;
        float pr = 0.0f, pi = 0.0f;
#pragma unroll
        for (int j = 0; j < 6; ++j) {
            int x = lane + 32 * j;
            float ar = g_Ar[m * NPIX + x];
            float ai = g_Ai[m * NPIX + x];
            float tr = accr[mi][j], ti = acci[mi][j];
            pr = fmaf(ar, tr, pr);  pr = fmaf(-ai, ti, pr);
            pi = fmaf(ar, ti, pi);  pi = fmaf(ai, tr, pi);
        }
#pragma unroll
        for (int o = 16; o > 0; o >>= 1) {
            pr += __shfl_xor_sync(0xffffffffu, pr, o);
            pi += __shfl_xor_sync(0xffffffffu, pi, o);
        }
        if (lane == 0) { g_sre[m] = pr; g_sim[m] = pi; }
    }
}

// -------------------- adjoint: out[x,y] = sum_m conjA[m,x] d[m] conjB[m,y] ----
// Split-K over NCHUNK m-chunks; E = conj(A)*d computed during the smem stage.
// grid (4, 4, NCHUNK), block 256 (16x16), thread tile 3x3, out tile 48x48.
__global__ void __launch_bounds__(256) k_adj() {
    __shared__ float sEr[32][48];
    __shared__ float sEi[32][48];
    __shared__ float sCr[32][48];   // Br tile (conj applied in the MAC)
    __shared__ float sCi[32][48];

    int x0    = blockIdx.x * 48;
    int y0    = blockIdx.y * 48;
    int mbase = blockIdx.z * KCHUNK;
    int t  = threadIdx.x;
    int tx = t & 15;        // -> y (coalesced partial writes)
    int ty = t >> 4;        // -> x

    float accr[3][3], acci[3][3];
#pragma unroll
    for (int a = 0; a < 3; ++a)
#pragma unroll
        for (int b = 0; b < 3; ++b) { accr[a][b] = 0.0f; acci[a][b] = 0.0f; }

    for (int kk = 0; kk < KCHUNK; kk += 32) {
        for (int i = t; i < 32 * 48; i += 256) {
            int ml = i / 48, c = i - ml * 48;
            int m  = mbase + kk + ml;
            float dr = g_dre[m], di = g_dim[m];
            float ar = g_Ar[m * NPIX + x0 + c];
            float ai = g_Ai[m * NPIX + x0 + c];
            sEr[ml][c] = fmaf(ar, dr,  ai * di);   // (Ar - iAi)(dr + idi).re
            sEi[ml][c] = fmaf(ar, di, -ai * dr);   //                     .im
            sCr[ml][c] = g_Br[m * NPIX + y0 + c];
            sCi[ml][c] = g_Bi[m * NPIX + y0 + c];
        }
        __syncthreads();

#pragma unroll 8
        for (int k = 0; k < 32; ++k) {
            float er[3], ei[3], br[3], bi[3];
#pragma unroll
            for (int a = 0; a < 3; ++a) {
                er[a] = sEr[k][ty + 16 * a];
                ei[a] = sEi[k][ty + 16 * a];
                br[a] = sCr[k][tx + 16 * a];
                bi[a] = sCi[k][tx + 16 * a];
            }
#pragma unroll
            for (int a = 0; a < 3; ++a)
#pragma unroll
                for (int b = 0; b < 3; ++b) {
                    // out += E * conj(B)
                    accr[a][b] = fmaf(er[a], br[b], accr[a][b]);
                    accr[a][b] = fmaf(ei[a], bi[b], accr[a][b]);
                    acci[a][b] = fmaf(ei[a], br[b], acci[a][b]);
                    acci[a][b] = fmaf(-er[a], bi[b], acci[a][b]);
                }
        }
        __syncthreads();
    }

    float* __restrict__ pp = g_part + blockIdx.z * (2 * NN);
#pragma unroll
    for (int a = 0; a < 3; ++a) {
        int x = x0 + ty + 16 * a;
#pragma unroll
        for (int b = 0; b < 3; ++b) {
            int y = y0 + tx + 16 * b;
            pp[x * NPIX + y]      = accr[a][b];
            pp[NN + x * NPIX + y] = acci[a][b];
        }
    }
}

// -------------------- split-K reduce ------------------------------------------
// mode 0: write pipe image transposed into g_imgwT ([y][x]).
// mode 1: write final (2,N,N) output.
__global__ void k_reduce(float* __restrict__ out, int mode) {
    int idx = blockIdx.x * blockDim.x + threadIdx.x;
    if (idx >= NN) return;
    float sr = 0.0f, si = 0.0f;
#pragma unroll 8
    for (int c = 0; c < NCHUNK; ++c) {
        sr += g_part[c * (2 * NN) + idx];
        si += g_part[c * (2 * NN) + NN + idx];
    }
    if (mode == 0) {
        int x = idx / NPIX, y = idx - (idx / NPIX) * NPIX;
        g_imgwT_re[y * NPIX + x] = sr;
        g_imgwT_im[y * NPIX + x] = si;
    } else {
        out[idx]      = sr;
        out[NN + idx] = si;
    }
}

// -------------------- driver ---------------------------------------------------
extern "C" void kernel_launch(void* const* d_in, const int* in_sizes, int n_in,
                              void* d_out, int out_size) {
    const float* xin  = (const float*)d_in[0];   // (2,192,192)
    const float* traj = (const float*)d_in[1];   // (36864,2)
    float* out = (float*)d_out;                  // (2,192,192)

    const int T = 256;
    k_build<<<(MPTS * NPIX + T - 1) / T, T>>>(traj);
    k_transpose_in<<<(NN + T - 1) / T, T>>>(xin);
    k_winit<<<(MPTS + T - 1) / T, T>>>();

    dim3 gadj(4, 4, NCHUNK);
    for (int it = 0; it < 3; ++it) {
        k_dfromw<<<(MPTS + T - 1) / T, T>>>();
        k_adj<<<gadj, 256>>>();
        k_reduce<<<(NN + T - 1) / T, T>>>(out, /*mode=*/0);
        k_op<<<MPTS / 16, 256>>>(/*src=*/1);
        k_wupdate<<<(MPTS + T - 1) / T, T>>>();
    }

    k_op<<<MPTS / 16, 256>>>(/*src=*/0);         // kspace = op(img)
    k_dscale<<<(MPTS + T - 1) / T, T>>>();       // d = w * kspace
    k_adj<<<gadj, 256>>>();
    k_reduce<<<(NN + T - 1) / T, T>>>(out, /*mode=*/1);
}

// round 2
// speedup vs baseline: 1.1001x; 1.1001x over previous
#include <cuda_runtime.h>
#include <math.h>

// ----------------------------------------------------------------------------
// Radial NUFFT pipeline (exact NDFT), N=192 image, M=36864 samples.
// f32x2 (packed FFMA2) version: both GEMM kernels use fma.rn.f32x2 to reach
// the full 128-FMA/cyc/SM fp32 datapath on sm_103a.
// ----------------------------------------------------------------------------

#define NPIX   192
#define MPTS   (NPIX * NPIX)        // 36864
#define NN     (NPIX * NPIX)
#define NCHUNK 64                    // split-K chunks for adjoint
#define KCHUNK (MPTS / NCHUNK)       // 576
#define TWO_PI_F 6.28318530717958647693f

typedef unsigned long long u64;
#define SGN2 0x8000000080000000ULL   // sign-bit mask for both halves of f32x2

// -------------------- f32x2 helpers ------------------------------------------
__device__ __forceinline__ u64 pk2(float lo, float hi) {
    u64 r; asm("mov.b64 %0, {%1,%2};" : "=l"(r) : "f"(lo), "f"(hi)); return r;
}
__device__ __forceinline__ u64 bc2(float v) { return pk2(v, v); }
__device__ __forceinline__ void fma2(u64& d, u64 a, u64 b) {
    asm("fma.rn.f32x2 %0, %1, %2, %0;" : "+l"(d) : "l"(a), "l"(b));
}
__device__ __forceinline__ float lo2(u64 v) {
    float a, b; asm("mov.b64 {%0,%1}, %2;" : "=f"(a), "=f"(b) : "l"(v)); return a;
}
__device__ __forceinline__ float hi2(u64 v) {
    float a, b; asm("mov.b64 {%0,%1}, %2;" : "=f"(a), "=f"(b) : "l"(v)); return b;
}
__device__ __forceinline__ float sum2(u64 v) { return lo2(v) + hi2(v); }

// -------------------- scratch (device globals; no allocations) --------------
static __device__ __align__(16) float g_Ar[MPTS * NPIX];
static __device__ __align__(16) float g_Ai[MPTS * NPIX];
static __device__ __align__(16) float g_Br[MPTS * NPIX];
static __device__ __align__(16) float g_Bi[MPTS * NPIX];

static __device__ __align__(16) float g_imgT_re[NN],  g_imgT_im[NN];   // [y][x]
static __device__ __align__(16) float g_imgwT_re[NN], g_imgwT_im[NN];  // [y][x]

static __device__ float g_w[MPTS];
static __device__ float g_dre[MPTS], g_dim[MPTS];
static __device__ float g_sre[MPTS], g_sim[MPTS];

static __device__ __align__(16) float g_part[NCHUNK * 2 * NN];

// -------------------- build A, B ---------------------------------------------
__global__ void k_build(const float* __restrict__ traj) {
    int idx = blockIdx.x * blockDim.x + threadIdx.x;
    if (idx >= MPTS * NPIX) return;
    int m = idx / NPIX;
    int x = idx - m * NPIX;
    float p  = (float)x - 96.0f;
    float kx = traj[2 * m];
    float ky = traj[2 * m + 1];

    float s, c, ph, r;
    ph = kx * p; r = ph - rintf(ph);
    __sincosf(TWO_PI_F * r, &s, &c);
    g_Ar[idx] = c;  g_Ai[idx] = -s;

    ph = ky * p; r = ph - rintf(ph);
    __sincosf(TWO_PI_F * r, &s, &c);
    g_Br[idx] = c;  g_Bi[idx] = -s;
}

// -------------------- image transpose ----------------------------------------
__global__ void k_transpose_in(const float* __restrict__ xin) {
    int idx = blockIdx.x * blockDim.x + threadIdx.x;
    if (idx >= NN) return;
    int x = idx / NPIX, y = idx - x * NPIX;
    g_imgT_re[y * NPIX + x] = xin[idx];
    g_imgT_im[y * NPIX + x] = xin[NN + idx];
}

// -------------------- tiny per-sample kernels --------------------------------
__global__ void k_winit() {
    int i = blockIdx.x * blockDim.x + threadIdx.x;
    if (i < MPTS) g_w[i] = 1.0f;
}
__global__ void k_dfromw() {
    int i = blockIdx.x * blockDim.x + threadIdx.x;
    if (i < MPTS) { g_dre[i] = g_w[i]; g_dim[i] = 0.0f; }
}
__global__ void k_wupdate() {
    int i = blockIdx.x * blockDim.x + threadIdx.x;
    if (i < MPTS) {
        float qr = g_sre[i], qi = g_sim[i];
        float mag = sqrtf(qr * qr + qi * qi);
        g_w[i] = g_w[i] / fmaxf(mag, 1e-20f);
    }
}
__global__ void k_dscale() {
    int i = blockIdx.x * blockDim.x + threadIdx.x;
    if (i < MPTS) {
        float w = g_w[i];
        g_dre[i] = w * g_sre[i];
        g_dim[i] = w * g_sim[i];
    }
}

// -------------------- forward op ----------------------------------------------
// s[m] = sum_x A[m,x] * (sum_y B[m,y] img[x,y]).
// Thread owns x = 2*lane + 64*j (3 f32x2 pairs), warp owns 2 m's.
__global__ void __launch_bounds__(256) k_op(int src) {
    __shared__ float sIr[16][192];
    __shared__ float sIi[16][192];
    __shared__ float sBr[16][16];
    __shared__ float sBi[16][16];

    const float* __restrict__ gTr = src ? g_imgwT_re : g_imgT_re;
    const float* __restrict__ gTi = src ? g_imgwT_im : g_imgT_im;

    int m0   = blockIdx.x * 16;
    int t    = threadIdx.x;
    int lane = t & 31;
    int wrp  = t >> 5;

    u64 accr[2][3], acci[2][3];
#pragma unroll
    for (int a = 0; a < 2; ++a)
#pragma unroll
        for (int j = 0; j < 3; ++j) { accr[a][j] = 0ULL; acci[a][j] = 0ULL; }

    for (int y0 = 0; y0 < NPIX; y0 += 16) {
        for (int i = t; i < 16 * 192; i += 256) {
            int yl = i / 192, x = i - yl * 192;
            sIr[yl][x] = gTr[(y0 + yl) * NPIX + x];
            sIi[yl][x] = gTi[(y0 + yl) * NPIX + x];
        }
        {
            int ml = t >> 4, yl = t & 15;
            sBr[ml][yl] = g_Br[(m0 + ml) * NPIX + y0 + yl];
            sBi[ml][yl] = g_Bi[(m0 + ml) * NPIX + y0 + yl];
        }
        __syncthreads();

#pragma unroll
        for (int k = 0; k < 16; ++k) {
            u64 pbr0  = bc2(sBr[2 * wrp][k]);
            u64 pbi0  = bc2(sBi[2 * wrp][k]);
            u64 pnbi0 = pbi0 ^ SGN2;
            u64 pbr1  = bc2(sBr[2 * wrp + 1][k]);
            u64 pbi1  = bc2(sBi[2 * wrp + 1][k]);
            u64 pnbi1 = pbi1 ^ SGN2;
#pragma unroll
            for (int j = 0; j < 3; ++j) {
                int x = 2 * lane + 64 * j;
                u64 gr = *reinterpret_cast<const u64*>(&sIr[k][x]);
                u64 gi = *reinterpret_cast<const u64*>(&sIi[k][x]);
                fma2(accr[0][j], pbr0,  gr);
                fma2(accr[0][j], pnbi0, gi);
                fma2(acci[0][j], pbr0,  gi);
                fma2(acci[0][j], pbi0,  gr);
                fma2(accr[1][j], pbr1,  gr);
                fma2(accr[1][j], pnbi1, gi);
                fma2(acci[1][j], pbr1,  gi);
                fma2(acci[1][j], pbi1,  gr);
            }
        }
        __syncthreads();
    }

    // epilogue: k[m] = sum_x A[m,x] * t[m,x]  (no conj on forward op)
#pragma unroll
    for (int mi = 0; mi < 2; ++mi) {
        int m = m0 + 2 * wrp + mi;
        u64 prv = 0ULL, piv = 0ULL;
#pragma unroll
        for (int j = 0; j < 3; ++j) {
            int x = 2 * lane + 64 * j;
            u64 ar  = *reinterpret_cast<const u64*>(&g_Ar[m * NPIX + x]);
            u64 ai  = *reinterpret_cast<const u64*>(&g_Ai[m * NPIX + x]);
            u64 nai = ai ^ SGN2;
            fma2(prv, ar,  accr[mi][j]);
            fma2(prv, nai, acci[mi][j]);
            fma2(piv, ar,  acci[mi][j]);
            fma2(piv, ai,  accr[mi][j]);
        }
        float pr = sum2(prv), pi = sum2(piv);
#pragma unroll
        for (int o = 16; o > 0; o >>= 1) {
            pr += __shfl_xor_sync(0xffffffffu, pr, o);
            pi += __shfl_xor_sync(0xffffffffu, pi, o);
        }
        if (lane == 0) { g_sre[m] = pr; g_sim[m] = pi; }
    }
}

// -------------------- adjoint --------------------------------------------------
// out[x,y] = sum_m conj(A[m,x]) d[m] conj(B[m,y]).
// Out tile 48(x) x 64(y); thread tile 3(x) x 4(y), y vectorized as 2 f32x2.
// grid (4, 3, NCHUNK), block 256 (tx = y index, ty = x index).
__global__ void __launch_bounds__(256) k_adj() {
    __shared__ float sEr[32][48];
    __shared__ float sEi[32][48];
    __shared__ float sCr[32][64];
    __shared__ float sCi[32][64];

    int x0    = blockIdx.x * 48;
    int y0    = blockIdx.y * 64;
    int mbase = blockIdx.z * KCHUNK;
    int t  = threadIdx.x;
    int tx = t & 15;        // -> y
    int ty = t >> 4;        // -> x

    u64 accr[3][2], acci[3][2];
#pragma unroll
    for (int a = 0; a < 3; ++a)
#pragma unroll
        for (int p = 0; p < 2; ++p) { accr[a][p] = 0ULL; acci[a][p] = 0ULL; }

    for (int kk = 0; kk < KCHUNK; kk += 32) {
        // stage E = conj(A) * d over this block's x window
        for (int i = t; i < 32 * 48; i += 256) {
            int ml = i / 48, c = i - ml * 48;
            int m  = mbase + kk + ml;
            float dr = g_dre[m], di = g_dim[m];
            float ar = g_Ar[m * NPIX + x0 + c];
            float ai = g_Ai[m * NPIX + x0 + c];
            sEr[ml][c] = fmaf(ar, dr,  ai * di);
            sEi[ml][c] = fmaf(ar, di, -ai * dr);
        }
        // stage B tile over this block's y window
        for (int i = t; i < 32 * 64; i += 256) {
            int ml = i / 64, c = i - ml * 64;
            int m  = mbase + kk + ml;
            sCr[ml][c] = g_Br[m * NPIX + y0 + c];
            sCi[ml][c] = g_Bi[m * NPIX + y0 + c];
        }
        __syncthreads();

#pragma unroll 4
        for (int k = 0; k < 32; ++k) {
            u64 brv[2], biv[2];
#pragma unroll
            for (int p = 0; p < 2; ++p) {
                int y = 2 * tx + 32 * p;
                brv[p] = *reinterpret_cast<const u64*>(&sCr[k][y]);
                biv[p] = *reinterpret_cast<const u64*>(&sCi[k][y]);
            }
#pragma unroll
            for (int a = 0; a < 3; ++a) {
                u64 per  = bc2(sEr[k][ty + 16 * a]);
                u64 pei  = bc2(sEi[k][ty + 16 * a]);
                u64 pner = per ^ SGN2;
#pragma unroll
                for (int p = 0; p < 2; ++p) {
                    // out += E * conj(B):
                    // re += er*br + ei*bi ; im += ei*br - er*bi
                    fma2(accr[a][p], per,  brv[p]);
                    fma2(accr[a][p], pei,  biv[p]);
                    fma2(acci[a][p], pei,  brv[p]);
                    fma2(acci[a][p], pner, biv[p]);
                }
            }
        }
        __syncthreads();
    }

    float* __restrict__ pp = g_part + blockIdx.z * (2 * NN);
#pragma unroll
    for (int a = 0; a < 3; ++a) {
        int x = x0 + ty + 16 * a;
#pragma unroll
        for (int p = 0; p < 2; ++p) {
            int y = y0 + 2 * tx + 32 * p;
            *reinterpret_cast<u64*>(&pp[x * NPIX + y])      = accr[a][p];
            *reinterpret_cast<u64*>(&pp[NN + x * NPIX + y]) = acci[a][p];
        }
    }
}

// -------------------- split-K reduce ------------------------------------------
__global__ void k_reduce(float* __restrict__ out, int mode) {
    int idx = blockIdx.x * blockDim.x + threadIdx.x;
    if (idx >= NN) return;
    float sr = 0.0f, si = 0.0f;
#pragma unroll 8
    for (int c = 0; c < NCHUNK; ++c) {
        sr += g_part[c * (2 * NN) + idx];
        si += g_part[c * (2 * NN) + NN + idx];
    }
    if (mode == 0) {
        int x = idx / NPIX, y = idx - (idx / NPIX) * NPIX;
        g_imgwT_re[y * NPIX + x] = sr;
        g_imgwT_im[y * NPIX + x] = si;
    } else {
        out[idx]      = sr;
        out[NN + idx] = si;
    }
}

// -------------------- driver ---------------------------------------------------
extern "C" void kernel_launch(void* const* d_in, const int* in_sizes, int n_in,
                              void* d_out, int out_size) {
    const float* xin  = (const float*)d_in[0];   // (2,192,192)
    const float* traj = (const float*)d_in[1];   // (36864,2)
    float* out = (float*)d_out;                  // (2,192,192)

    const int T = 256;
    k_build<<<(MPTS * NPIX + T - 1) / T, T>>>(traj);
    k_transpose_in<<<(NN + T - 1) / T, T>>>(xin);
    k_winit<<<(MPTS + T - 1) / T, T>>>();

    dim3 gadj(4, 3, NCHUNK);
    for (int it = 0; it < 3; ++it) {
        k_dfromw<<<(MPTS + T - 1) / T, T>>>();
        k_adj<<<gadj, 256>>>();
        k_reduce<<<(NN + T - 1) / T, T>>>(out, /*mode=*/0);
        k_op<<<MPTS / 16, 256>>>(/*src=*/1);
        k_wupdate<<<(MPTS + T - 1) / T, T>>>();
    }

    k_op<<<MPTS / 16, 256>>>(/*src=*/0);         // kspace = op(img)
    k_dscale<<<(MPTS + T - 1) / T, T>>>();       // d = w * kspace
    k_adj<<<gadj, 256>>>();
    k_reduce<<<(NN + T - 1) / T, T>>>(out, /*mode=*/1);
}

// round 3
// speedup vs baseline: 1.1044x; 1.0040x over previous
#include <cuda_runtime.h>
#include <math.h>

// ----------------------------------------------------------------------------
// Radial NUFFT pipeline (exact NDFT), N=192 image, M=36864 samples.
// f32x2 (packed FFMA2) version: both GEMM kernels use fma.rn.f32x2 to reach
// the full 128-FMA/cyc/SM fp32 datapath on sm_103a.
// ----------------------------------------------------------------------------

#define NPIX   192
#define MPTS   (NPIX * NPIX)        // 36864
#define NN     (NPIX * NPIX)
#define NCHUNK 64                    // split-K chunks for adjoint
#define KCHUNK (MPTS / NCHUNK)       // 576
#define TWO_PI_F 6.28318530717958647693f

typedef unsigned long long u64;
#define SGN2 0x8000000080000000ULL   // sign-bit mask for both halves of f32x2

// -------------------- f32x2 helpers ------------------------------------------
__device__ __forceinline__ u64 pk2(float lo, float hi) {
    u64 r; asm("mov.b64 %0, {%1,%2};" : "=l"(r) : "f"(lo), "f"(hi)); return r;
}
__device__ __forceinline__ u64 bc2(float v) { return pk2(v, v); }
__device__ __forceinline__ void fma2(u64& d, u64 a, u64 b) {
    asm("fma.rn.f32x2 %0, %1, %2, %0;" : "+l"(d) : "l"(a), "l"(b));
}
__device__ __forceinline__ float lo2(u64 v) {
    float a, b; asm("mov.b64 {%0,%1}, %2;" : "=f"(a), "=f"(b) : "l"(v)); return a;
}
__device__ __forceinline__ float hi2(u64 v) {
    float a, b; asm("mov.b64 {%0,%1}, %2;" : "=f"(a), "=f"(b) : "l"(v)); return b;
}
__device__ __forceinline__ float sum2(u64 v) { return lo2(v) + hi2(v); }

// -------------------- scratch (device globals; no allocations) --------------
static __device__ __align__(16) float g_Ar[MPTS * NPIX];
static __device__ __align__(16) float g_Ai[MPTS * NPIX];
static __device__ __align__(16) float g_Br[MPTS * NPIX];
static __device__ __align__(16) float g_Bi[MPTS * NPIX];

static __device__ __align__(16) float g_imgT_re[NN],  g_imgT_im[NN];   // [y][x]
static __device__ __align__(16) float g_imgwT_re[NN], g_imgwT_im[NN];  // [y][x]

static __device__ float g_w[MPTS];
static __device__ float g_dre[MPTS], g_dim[MPTS];
static __device__ float g_sre[MPTS], g_sim[MPTS];

static __device__ __align__(16) float g_part[NCHUNK * 2 * NN];

// -------------------- build A, B ---------------------------------------------
__global__ void k_build(const float* __restrict__ traj) {
    int idx = blockIdx.x * blockDim.x + threadIdx.x;
    if (idx >= MPTS * NPIX) return;
    int m = idx / NPIX;
    int x = idx - m * NPIX;
    float p  = (float)x - 96.0f;
    float kx = traj[2 * m];
    float ky = traj[2 * m + 1];

    float s, c, ph, r;
    ph = kx * p; r = ph - rintf(ph);
    __sincosf(TWO_PI_F * r, &s, &c);
    g_Ar[idx] = c;  g_Ai[idx] = -s;

    ph = ky * p; r = ph - rintf(ph);
    __sincosf(TWO_PI_F * r, &s, &c);
    g_Br[idx] = c;  g_Bi[idx] = -s;
}

// -------------------- image transpose ----------------------------------------
__global__ void k_transpose_in(const float* __restrict__ xin) {
    int idx = blockIdx.x * blockDim.x + threadIdx.x;
    if (idx >= NN) return;
    int x = idx / NPIX, y = idx - x * NPIX;
    g_imgT_re[y * NPIX + x] = xin[idx];
    g_imgT_im[y * NPIX + x] = xin[NN + idx];
}

// -------------------- tiny per-sample kernels --------------------------------
__global__ void k_winit() {
    int i = blockIdx.x * blockDim.x + threadIdx.x;
    if (i < MPTS) g_w[i] = 1.0f;
}
__global__ void k_dfromw() {
    int i = blockIdx.x * blockDim.x + threadIdx.x;
    if (i < MPTS) { g_dre[i] = g_w[i]; g_dim[i] = 0.0f; }
}
__global__ void k_wupdate() {
    int i = blockIdx.x * blockDim.x + threadIdx.x;
    if (i < MPTS) {
        float qr = g_sre[i], qi = g_sim[i];
        float mag = sqrtf(qr * qr + qi * qi);
        g_w[i] = g_w[i] / fmaxf(mag, 1e-20f);
    }
}
__global__ void k_dscale() {
    int i = blockIdx.x * blockDim.x + threadIdx.x;
    if (i < MPTS) {
        float w = g_w[i];
        g_dre[i] = w * g_sre[i];
        g_dim[i] = w * g_sim[i];
    }
}

// -------------------- forward op ----------------------------------------------
// s[m] = sum_x A[m,x] * (sum_y B[m,y] img[x,y]).
// Thread owns x = 2*lane + 64*j (3 f32x2 pairs), warp owns 2 m's.
__global__ void __launch_bounds__(256) k_op(int src) {
    __shared__ float sIr[16][192];
    __shared__ float sIi[16][192];
    __shared__ float sBr[16][16];
    __shared__ float sBi[16][16];

    const float* __restrict__ gTr = src ? g_imgwT_re : g_imgT_re;
    const float* __restrict__ gTi = src ? g_imgwT_im : g_imgT_im;

    int m0   = blockIdx.x * 16;
    int t    = threadIdx.x;
    int lane = t & 31;
    int wrp  = t >> 5;

    u64 accr[2][3], acci[2][3];
#pragma unroll
    for (int a = 0; a < 2; ++a)
#pragma unroll
        for (int j = 0; j < 3; ++j) { accr[a][j] = 0ULL; acci[a][j] = 0ULL; }

    for (int y0 = 0; y0 < NPIX; y0 += 16) {
        for (int i = t; i < 16 * 192; i += 256) {
            int yl = i / 192, x = i - yl * 192;
            sIr[yl][x] = gTr[(y0 + yl) * NPIX + x];
            sIi[yl][x] = gTi[(y0 + yl) * NPIX + x];
        }
        {
            int ml = t >> 4, yl = t & 15;
            sBr[ml][yl] = g_Br[(m0 + ml) * NPIX + y0 + yl];
            sBi[ml][yl] = g_Bi[(m0 + ml) * NPIX + y0 + yl];
        }
        __syncthreads();

#pragma unroll
        for (int k = 0; k < 16; ++k) {
            u64 pbr0  = bc2(sBr[2 * wrp][k]);
            u64 pbi0  = bc2(sBi[2 * wrp][k]);
            u64 pnbi0 = pbi0 ^ SGN2;
            u64 pbr1  = bc2(sBr[2 * wrp + 1][k]);
            u64 pbi1  = bc2(sBi[2 * wrp + 1][k]);
            u64 pnbi1 = pbi1 ^ SGN2;
#pragma unroll
            for (int j = 0; j < 3; ++j) {
                int x = 2 * lane + 64 * j;
                u64 gr = *reinterpret_cast<const u64*>(&sIr[k][x]);
                u64 gi = *reinterpret_cast<const u64*>(&sIi[k][x]);
                fma2(accr[0][j], pbr0,  gr);
                fma2(accr[0][j], pnbi0, gi);
                fma2(acci[0][j], pbr0,  gi);
                fma2(acci[0][j], pbi0,  gr);
                fma2(accr[1][j], pbr1,  gr);
                fma2(accr[1][j], pnbi1, gi);
                fma2(acci[1][j], pbr1,  gi);
                fma2(acci[1][j], pbi1,  gr);
            }
        }
        __syncthreads();
    }

    // epilogue: k[m] = sum_x A[m,x] * t[m,x]  (no conj on forward op)
#pragma unroll
    for (int mi = 0; mi < 2; ++mi) {
        int m = m0 + 2 * wrp + mi;
        u64 prv = 0ULL, piv = 0ULL;
#pragma unroll
        for (int j = 0; j < 3; ++j) {
            int x = 2 * lane + 64 * j;
            u64 ar  = *reinterpret_cast<const u64*>(&g_Ar[m * NPIX + x]);
            u64 ai  = *reinterpret_cast<const u64*>(&g_Ai[m * NPIX + x]);
            u64 nai = ai ^ SGN2;
            fma2(prv, ar,  accr[mi][j]);
            fma2(prv, nai, acci[mi][j]);
            fma2(piv, ar,  acci[mi][j]);
            fma2(piv, ai,  accr[mi][j]);
        }
        float pr = sum2(prv), pi = sum2(piv);
#pragma unroll
        for (int o = 16; o > 0; o >>= 1) {
            pr += __shfl_xor_sync(0xffffffffu, pr, o);
            pi += __shfl_xor_sync(0xffffffffu, pi, o);
        }
        if (lane == 0) { g_sre[m] = pr; g_sim[m] = pi; }
    }
}

// -------------------- adjoint --------------------------------------------------
// out[x,y] = sum_m conj(A[m,x]) d[m] conj(B[m,y]).
// Out tile 48(x) x 64(y); thread tile 3(x) x 4(y), y vectorized as 2 f32x2.
// grid (4, 3, NCHUNK), block 256 (tx = y index, ty = x index).
__global__ void __launch_bounds__(256) k_adj() {
    __shared__ float sEr[32][48];
    __shared__ float sEi[32][48];
    __shared__ float sCr[32][64];
    __shared__ float sCi[32][64];

    int x0    = blockIdx.x * 48;
    int y0    = blockIdx.y * 64;
    int mbase = blockIdx.z * KCHUNK;
    int t  = threadIdx.x;
    int tx = t & 15;        // -> y
    int ty = t >> 4;        // -> x

    u64 accr[3][2], acci[3][2];
#pragma unroll
    for (int a = 0; a < 3; ++a)
#pragma unroll
        for (int p = 0; p < 2; ++p) { accr[a][p] = 0ULL; acci[a][p] = 0ULL; }

    for (int kk = 0; kk < KCHUNK; kk += 32) {
        // stage E = conj(A) * d over this block's x window
        for (int i = t; i < 32 * 48; i += 256) {
            int ml = i / 48, c = i - ml * 48;
            int m  = mbase + kk + ml;
            float dr = g_dre[m], di = g_dim[m];
            float ar = g_Ar[m * NPIX + x0 + c];
            float ai = g_Ai[m * NPIX + x0 + c];
            sEr[ml][c] = fmaf(ar, dr,  ai * di);
            sEi[ml][c] = fmaf(ar, di, -ai * dr);
        }
        // stage B tile over this block's y window
        for (int i = t; i < 32 * 64; i += 256) {
            int ml = i / 64, c = i - ml * 64;
            int m  = mbase + kk + ml;
            sCr[ml][c] = g_Br[m * NPIX + y0 + c];
            sCi[ml][c] = g_Bi[m * NPIX + y0 + c];
        }
        __syncthreads();

#pragma unroll 4
        for (int k = 0; k < 32; ++k) {
            u64 brv[2], biv[2];
#pragma unroll
            for (int p = 0; p < 2; ++p) {
                int y = 2 * tx + 32 * p;
                brv[p] = *reinterpret_cast<const u64*>(&sCr[k][y]);
                biv[p] = *reinterpret_cast<const u64*>(&sCi[k][y]);
            }
#pragma unroll
            for (int a = 0; a < 3; ++a) {
                u64 per  = bc2(sEr[k][ty + 16 * a]);
                u64 pei  = bc2(sEi[k][ty + 16 * a]);
                u64 pner = per ^ SGN2;
#pragma unroll
                for (int p = 0; p < 2; ++p) {
                    // out += E * conj(B):
                    // re += er*br + ei*bi ; im += ei*br - er*bi
                    fma2(accr[a][p], per,  brv[p]);
                    fma2(accr[a][p], pei,  biv[p]);
                    fma2(acci[a][p], pei,  brv[p]);
                    fma2(acci[a][p], pner, biv[p]);
                }
            }
        }
        __syncthreads();
    }

    float* __restrict__ pp = g_part + blockIdx.z * (2 * NN);
#pragma unroll
    for (int a = 0; a < 3; ++a) {
        int x = x0 + ty + 16 * a;
#pragma unroll
        for (int p = 0; p < 2; ++p) {
            int y = y0 + 2 * tx + 32 * p;
            *reinterpret_cast<u64*>(&pp[x * NPIX + y])      = accr[a][p];
            *reinterpret_cast<u64*>(&pp[NN + x * NPIX + y]) = acci[a][p];
        }
    }
}

// -------------------- split-K reduce ------------------------------------------
__global__ void k_reduce(float* __restrict__ out, int mode) {
    int idx = blockIdx.x * blockDim.x + threadIdx.x;
    if (idx >= NN) return;
    float sr = 0.0f, si = 0.0f;
#pragma unroll 8
    for (int c = 0; c < NCHUNK; ++c) {
        sr += g_part[c * (2 * NN) + idx];
        si += g_part[c * (2 * NN) + NN + idx];
    }
    if (mode == 0) {
        int x = idx / NPIX, y = idx - (idx / NPIX) * NPIX;
        g_imgwT_re[y * NPIX + x] = sr;
        g_imgwT_im[y * NPIX + x] = si;
    } else {
        out[idx]      = sr;
        out[NN + idx] = si;
    }
}

// -------------------- driver ---------------------------------------------------
extern "C" void kernel_launch(void* const* d_in, const int* in_sizes, int n_in,
                              void* d_out, int out_size) {
    const float* xin  = (const float*)d_in[0];   // (2,192,192)
    const float* traj = (const float*)d_in[1];   // (36864,2)
    float* out = (float*)d_out;                  // (2,192,192)

    const int T = 256;
    k_build<<<(MPTS * NPIX + T - 1) / T, T>>>(traj);
    k_transpose_in<<<(NN + T - 1) / T, T>>>(xin);
    k_winit<<<(MPTS + T - 1) / T, T>>>();

    dim3 gadj(4, 3, NCHUNK);
    for (int it = 0; it < 3; ++it) {
        k_dfromw<<<(MPTS + T - 1) / T, T>>>();
        k_adj<<<gadj, 256>>>();
        k_reduce<<<(NN + T - 1) / T, T>>>(out, /*mode=*/0);
        k_op<<<MPTS / 16, 256>>>(/*src=*/1);
        k_wupdate<<<(MPTS + T - 1) / T, T>>>();
    }

    k_op<<<MPTS / 16, 256>>>(/*src=*/0);         // kspace = op(img)
    k_dscale<<<(MPTS + T - 1) / T, T>>>();       // d = w * kspace
    k_adj<<<gadj, 256>>>();
    k_reduce<<<(NN + T - 1) / T, T>>>(out, /*mode=*/1);
}